// round 2
// baseline (speedup 1.0000x reference)
#include <cuda_runtime.h>
#include <cuda_bf16.h>
#include <cstdint>

// Problem constants (fixed by the reference):
//   B=4, S=4096 -> T = 16384 tokens
//   IN_F = OUT_F = 4096, G = 32, GS = GO = 128
#define GROUPS   32
#define GS_K     128
#define GO_N     128
#define IN_F     4096
#define TILE_T   128
#define NTHREADS 256

// Canonical int32 permutation, filled by convert_perm_kernel.
__device__ int g_perm[IN_F];

// Detect whether the perm buffer is int64 or int32 and normalize to int32.
// Viewed as int32: int64 storage of values <4096 gives zero at every odd
// index; an int32 permutation of 0..4095 has at most ONE zero anywhere.
// So "odd slots 1,3,...,15 all zero" <=> int64 storage.
__global__ void convert_perm_kernel(const int* __restrict__ p32)
{
    __shared__ int is64;
    if (threadIdx.x == 0) {
        int all0 = 1;
        #pragma unroll
        for (int i = 1; i < 16; i += 2) all0 &= (p32[i] == 0);
        is64 = all0;
    }
    __syncthreads();
    const int w = is64;
    for (int i = threadIdx.x; i < IN_F; i += blockDim.x)
        g_perm[i] = w ? p32[2 * i] : p32[i];
}

// One CTA: 128 tokens x one group. Full K=128 GEMM:
//   out[t, g*128+go] = sum_k x[t, perm[g*128+k]] * W[g, go, k] + b[g, go]
__global__ __launch_bounds__(NTHREADS, 1)
void bdl_fp32_kernel(const float* __restrict__ x,
                     const float* __restrict__ W,
                     const float* __restrict__ bias,
                     float* __restrict__ out,
                     int T)
{
    extern __shared__ float smem[];
    float* xs = smem;                                  // [128][128] k-major
    float* ws = smem + 128 * 128;                      // [128][128] k-major
    int*   idxs = (int*)(smem + 2 * 128 * 128);        // 128 ints
    float* bs = smem + 2 * 128 * 128 + 128;            // 128 floats

    const int g   = blockIdx.x;             // group fastest -> L2 reuse of x tile
    const int t0  = blockIdx.y * TILE_T;
    const int tid = threadIdx.x;

    if (tid < 128) {
        idxs[tid] = g_perm[g * GS_K + tid];
        bs[tid]   = bias[g * GO_N + tid];
    }
    __syncthreads();

    // --- W[g] -> ws[k][go] (transpose). STS conflict-free (go lane-fast). ---
    {
        const float* Wg = W + (size_t)g * (GO_N * GS_K);
        #pragma unroll
        for (int e = tid; e < GO_N * GS_K; e += NTHREADS) {
            const int go = e & 127;
            const int k  = e >> 7;
            ws[k * 128 + go] = Wg[go * GS_K + k];
        }
    }

    // --- Gathered x tile -> xs[k][t]. STS conflict-free (t lane-fast). ---
    #pragma unroll
    for (int e = tid; e < TILE_T * GS_K; e += NTHREADS) {
        const int t = e & 127;
        const int k = e >> 7;
        xs[k * 128 + t] = x[(size_t)(t0 + t) * IN_F + idxs[k]];
    }
    __syncthreads();

    // --- Mainloop: 8x8 register micro-tile per thread (256 thr = 128x128) ---
    const int tx = tid & 15;   // output cols [tx*8, tx*8+8)
    const int ty = tid >> 4;   // token rows  [ty*8, ty*8+8)

    float acc[8][8];
    #pragma unroll
    for (int i = 0; i < 8; ++i)
        #pragma unroll
        for (int j = 0; j < 8; ++j)
            acc[i][j] = 0.0f;

    const float* xrow = xs + (ty << 3);
    const float* wrow = ws + (tx << 3);

    #pragma unroll 8
    for (int k = 0; k < GS_K; ++k) {
        const float4 xa = *(const float4*)(xrow + k * 128);
        const float4 xb = *(const float4*)(xrow + k * 128 + 4);
        const float4 wa = *(const float4*)(wrow + k * 128);
        const float4 wb = *(const float4*)(wrow + k * 128 + 4);
        const float xr[8] = {xa.x, xa.y, xa.z, xa.w, xb.x, xb.y, xb.z, xb.w};
        const float wr[8] = {wa.x, wa.y, wa.z, wa.w, wb.x, wb.y, wb.z, wb.w};
        #pragma unroll
        for (int i = 0; i < 8; ++i)
            #pragma unroll
            for (int j = 0; j < 8; ++j)
                acc[i][j] = fmaf(xr[i], wr[j], acc[i][j]);
    }

    // --- Epilogue: bias + coalesced float4 stores ---
    const float4 b0 = *(const float4*)(bs + (tx << 3));
    const float4 b1 = *(const float4*)(bs + (tx << 3) + 4);
    #pragma unroll
    for (int i = 0; i < 8; ++i) {
        const size_t row = (size_t)(t0 + (ty << 3) + i) * IN_F + g * GO_N + (tx << 3);
        float4 o0, o1;
        o0.x = acc[i][0] + b0.x;  o0.y = acc[i][1] + b0.y;
        o0.z = acc[i][2] + b0.z;  o0.w = acc[i][3] + b0.w;
        o1.x = acc[i][4] + b1.x;  o1.y = acc[i][5] + b1.y;
        o1.z = acc[i][6] + b1.z;  o1.w = acc[i][7] + b1.w;
        *(float4*)(out + row)     = o0;
        *(float4*)(out + row + 4) = o1;
    }
}

extern "C" void kernel_launch(void* const* d_in, const int* in_sizes, int n_in,
                              void* d_out, int out_size)
{
    const float* x    = (const float*)d_in[0];   // [T, 4096] f32
    const int*   perm = (const int*)d_in[1];     // [4096] i32 (or i64; detected)
    const float* W    = (const float*)d_in[2];   // [32,128,128] f32
    const float* bias = (const float*)d_in[3];   // [32,128] f32
    float* out = (float*)d_out;                  // [T, 4096] f32

    const int T = in_sizes[0] / IN_F;            // 16384

    convert_perm_kernel<<<1, 1024>>>(perm);

    const int smem_bytes = (2 * 128 * 128 + 256) * (int)sizeof(float);  // ~129.5 KB
    cudaFuncSetAttribute(bdl_fp32_kernel,
                         cudaFuncAttributeMaxDynamicSharedMemorySize, smem_bytes);

    dim3 grid(GROUPS, T / TILE_T);   // (32, 128)
    dim3 block(NTHREADS);
    bdl_fp32_kernel<<<grid, block, smem_bytes>>>(x, W, bias, out, T);
}

// round 4
// speedup vs baseline: 2.9251x; 2.9251x over previous
#include <cuda_runtime.h>
#include <cuda_bf16.h>
#include <cstdint>

// Problem: B=4,S=4096 -> T=16384 tokens; IN_F=OUT_F=4096; G=32; GS=GO=128.
// y[t, g*128+n] = sum_k x[t, perm[g*128+k]] * W[g,n,k] + b[g,n]
#define IN_F   4096
#define G      32
#define TMAX   16384
#define TILE_T 128

// ---------------- device scratch (static; no allocation) ----------------
__device__ int           g_perm[IN_F];
__device__ uint32_t      g_whf[64 * 4096];             // W hi, B-fragment order per half-group
__device__ uint32_t      g_wlf[64 * 4096];             // W lo
__device__ __nv_bfloat16 g_xh[(size_t)TMAX * IN_F];    // permuted x hi
__device__ __nv_bfloat16 g_xl[(size_t)TMAX * IN_F];    // permuted x lo

__device__ __forceinline__ uint32_t smem_u32(const void* p) {
    uint32_t a;
    asm("{ .reg .u64 t; cvta.to.shared.u64 t, %1; cvt.u32.u64 %0, t; }" : "=r"(a) : "l"(p));
    return a;
}

__device__ __forceinline__ void split_pack(float v0, float v1, uint32_t& hp, uint32_t& lp) {
    __nv_bfloat16 h0 = __float2bfloat16(v0), h1 = __float2bfloat16(v1);
    __nv_bfloat16 l0 = __float2bfloat16(v0 - __bfloat162float(h0));
    __nv_bfloat16 l1 = __float2bfloat16(v1 - __bfloat162float(h1));
    hp = ((uint32_t)__bfloat16_as_ushort(h1) << 16) | __bfloat16_as_ushort(h0);
    lp = ((uint32_t)__bfloat16_as_ushort(l1) << 16) | __bfloat16_as_ushort(l0);
}

// ---------------- pass 0a: normalize perm (int64-or-int32 -> int32) ----------------
__global__ void convert_perm_kernel(const int* __restrict__ p32) {
    __shared__ int is64;
    if (threadIdx.x == 0) {
        int all0 = 1;
        #pragma unroll
        for (int i = 1; i < 16; i += 2) all0 &= (p32[i] == 0);
        is64 = all0;
    }
    __syncthreads();
    const int w = is64;
    for (int i = threadIdx.x; i < IN_F; i += blockDim.x)
        g_perm[i] = w ? p32[2 * i] : p32[i];
}

// ---------------- pass 0b: W -> split bf16 in mma.sync B-fragment order ----------------
// Fragment u32 index e within a half-group (64 outputs):
//   r=e&1, lane=(e>>1)&31, ks=(e>>6)&7, nt=e>>9 (0..7)
//   n = nbase + nt*8 + lane/4 ; k0 = ks*16 + 2*(lane&3) + (r?8:0)
//   value = {W[n][k0+1], W[n][k0]} packed bf16x2
__global__ void wprep_kernel(const float* __restrict__ W) {
    const int hg = blockIdx.x;            // 0..63 half-groups
    const int g = hg >> 1;
    const int nbase = (hg & 1) * 64;
    for (int e = threadIdx.x; e < 4096; e += blockDim.x) {
        const int r    = e & 1;
        const int lane = (e >> 1) & 31;
        const int ks   = (e >> 6) & 7;
        const int nt   = e >> 9;
        const int n    = nbase + nt * 8 + (lane >> 2);
        const int k0   = ks * 16 + 2 * (lane & 3) + (r ? 8 : 0);
        const float v0 = W[((size_t)g * 128 + n) * 128 + k0];
        const float v1 = W[((size_t)g * 128 + n) * 128 + k0 + 1];
        uint32_t hp, lp; split_pack(v0, v1, hp, lp);
        g_whf[hg * 4096 + e] = hp;
        g_wlf[hg * 4096 + e] = lp;
    }
}

// ---------------- pass 1: permute + split x (coalesced in and out) ----------------
__global__ __launch_bounds__(256) void xprep_kernel(const float* __restrict__ x) {
    __shared__ float row[IN_F];
    const int t = blockIdx.x;
    const float4* src = (const float4*)(x + (size_t)t * IN_F);
    for (int i = threadIdx.x; i < IN_F / 4; i += 256) ((float4*)row)[i] = src[i];
    __syncthreads();
    uint32_t* oh = (uint32_t*)(g_xh + (size_t)t * IN_F);
    uint32_t* ol = (uint32_t*)(g_xl + (size_t)t * IN_F);
    for (int j = threadIdx.x; j < IN_F / 2; j += 256) {
        const float v0 = row[g_perm[2 * j]];
        const float v1 = row[g_perm[2 * j + 1]];
        uint32_t hp, lp; split_pack(v0, v1, hp, lp);
        oh[j] = hp; ol[j] = lp;
    }
}

// ---------------- pass 2: HMMA block-diagonal GEMM ----------------
// CTA tile: 128 tokens x 64 outputs (one half-group), K=128, 3 bf16 products.
// smem: A hi/lo swizzled [128][256B] + B hi/lo fragment-order = 96 KB -> 2 CTA/SM.
#define SM_AH 0
#define SM_AL 32768
#define SM_BH 65536
#define SM_BL 81920
#define SM_SZ 98304

__global__ __launch_bounds__(256, 2)
void bdl_mma_kernel(const float* __restrict__ bias, float* __restrict__ out)
{
    extern __shared__ char smem[];
    const uint32_t sb = smem_u32(smem);
    const int hg = blockIdx.x;            // half-group
    const int g  = hg >> 1;
    const int t0 = blockIdx.y * TILE_T;
    const int tid = threadIdx.x, lane = tid & 31, wid = tid >> 5;

    // --- load A tiles (coalesced u32 from permuted-split x; XOR-swizzled STS) ---
    {
        const uint32_t* xh = (const uint32_t*)g_xh;
        const uint32_t* xl = (const uint32_t*)g_xl;
        #pragma unroll 8
        for (int e = tid; e < 8192; e += 256) {
            const int t = e >> 6, kp = e & 63;
            const size_t src = (size_t)(t0 + t) * (IN_F / 2) + g * 64 + kp;
            const uint32_t off = (uint32_t)t * 256
                               + ((((uint32_t)kp >> 2) ^ ((uint32_t)t & 7)) << 4)
                               + ((uint32_t)kp & 3) * 4;
            *(uint32_t*)(smem + SM_AH + off) = xh[src];
            *(uint32_t*)(smem + SM_AL + off) = xl[src];
        }
    }
    // --- load B tiles (linear copy, already fragment-ordered; L2-hot) ---
    {
        const uint4* bh = (const uint4*)(g_whf + hg * 4096);
        const uint4* bl = (const uint4*)(g_wlf + hg * 4096);
        uint4* sh = (uint4*)(smem + SM_BH);
        uint4* sl = (uint4*)(smem + SM_BL);
        #pragma unroll 4
        for (int i = tid; i < 1024; i += 256) { sh[i] = bh[i]; sl[i] = bl[i]; }
    }
    __syncthreads();

    // --- mainloop: warp grid 2(m) x 4(n); warp tile 64 x 16 ---
    const int wm = wid & 1;       // token half: rows [wm*64, wm*64+64)
    const int wn = wid >> 1;      // output slice: cols [wn*16, wn*16+16)

    float acc[4][2][4];
    #pragma unroll
    for (int mt = 0; mt < 4; ++mt)
        #pragma unroll
        for (int nt = 0; nt < 2; ++nt)
            #pragma unroll
            for (int q = 0; q < 4; ++q) acc[mt][nt][q] = 0.0f;

    #pragma unroll
    for (int p = 0; p < 3; ++p) {
        const uint32_t abase = sb + (p == 2 ? SM_AL : SM_AH);
        const uint32_t bbase = sb + (p == 1 ? SM_BL : SM_BH);
        #pragma unroll
        for (int ks = 0; ks < 8; ++ks) {
            uint32_t af[4][4];
            #pragma unroll
            for (int mt = 0; mt < 4; ++mt) {
                const uint32_t row = (uint32_t)(wm * 64 + mt * 16 + (lane & 15));
                const uint32_t c   = (uint32_t)(2 * ks + (lane >> 4));
                const uint32_t adr = abase + row * 256 + ((c ^ (row & 7)) << 4);
                asm volatile("ldmatrix.sync.aligned.m8n8.x4.shared.b16 {%0,%1,%2,%3}, [%4];"
                             : "=r"(af[mt][0]), "=r"(af[mt][1]), "=r"(af[mt][2]), "=r"(af[mt][3])
                             : "r"(adr));
            }
            uint32_t bf[2][2];
            #pragma unroll
            for (int nt = 0; nt < 2; ++nt) {
                const uint32_t adr = bbase + (uint32_t)(((wn * 2 + nt) * 8 + ks) * 32 + lane) * 8;
                asm volatile("ld.shared.v2.b32 {%0,%1}, [%2];"
                             : "=r"(bf[nt][0]), "=r"(bf[nt][1]) : "r"(adr));
            }
            #pragma unroll
            for (int mt = 0; mt < 4; ++mt)
                #pragma unroll
                for (int nt = 0; nt < 2; ++nt) {
                    asm volatile(
                        "mma.sync.aligned.m16n8k16.row.col.f32.bf16.bf16.f32 "
                        "{%0,%1,%2,%3}, {%4,%5,%6,%7}, {%8,%9}, {%0,%1,%2,%3};"
                        : "+f"(acc[mt][nt][0]), "+f"(acc[mt][nt][1]),
                          "+f"(acc[mt][nt][2]), "+f"(acc[mt][nt][3])
                        : "r"(af[mt][0]), "r"(af[mt][1]), "r"(af[mt][2]), "r"(af[mt][3]),
                          "r"(bf[nt][0]), "r"(bf[nt][1]));
                }
        }
    }

    // --- epilogue: bias + st.v2 stores (c-fragment layout) ---
    const int colbase = g * 128 + (hg & 1) * 64 + wn * 16;
    #pragma unroll
    for (int nt = 0; nt < 2; ++nt) {
        const int col = colbase + nt * 8 + 2 * (lane & 3);
        const float b0 = bias[col], b1 = bias[col + 1];
        #pragma unroll
        for (int mt = 0; mt < 4; ++mt) {
            const int r0 = t0 + wm * 64 + mt * 16 + (lane >> 2);
            float2 v0 = make_float2(acc[mt][nt][0] + b0, acc[mt][nt][1] + b1);
            float2 v1 = make_float2(acc[mt][nt][2] + b0, acc[mt][nt][3] + b1);
            *(float2*)(out + (size_t)r0 * IN_F + col)       = v0;
            *(float2*)(out + (size_t)(r0 + 8) * IN_F + col) = v1;
        }
    }
}

// ---------------- launch ----------------
extern "C" void kernel_launch(void* const* d_in, const int* in_sizes, int n_in,
                              void* d_out, int out_size)
{
    const float* x    = (const float*)d_in[0];
    const int*   perm = (const int*)d_in[1];
    const float* W    = (const float*)d_in[2];
    const float* bias = (const float*)d_in[3];
    float* out = (float*)d_out;

    const int T = in_sizes[0] / IN_F;   // 16384

    convert_perm_kernel<<<1, 1024>>>(perm);
    wprep_kernel<<<64, 256>>>(W);
    xprep_kernel<<<T, 256>>>(x);

    cudaFuncSetAttribute(bdl_mma_kernel,
                         cudaFuncAttributeMaxDynamicSharedMemorySize, SM_SZ);
    dim3 grid(64, T / TILE_T);          // (64 half-groups, 128 token tiles)
    bdl_mma_kernel<<<grid, 256, SM_SZ>>>(bias, out);
}

// round 5
// speedup vs baseline: 2.9954x; 1.0240x over previous
#include <cuda_runtime.h>
#include <cuda_bf16.h>
#include <cstdint>

// Problem: B=4,S=4096 -> T=16384 tokens; IN_F=OUT_F=4096; G=32; GS=GO=128.
// y[t, g*128+n] = sum_k x[t, perm[g*128+k]] * W[g,n,k] + b[g,n]
#define IN_F   4096
#define G      32
#define TMAX   16384
#define TILE_T 128

// ---------------- device scratch (static; no allocation) ----------------
__device__ int      g_perm[IN_F];
__device__ uint32_t g_whf[64 * 4096];           // W hi, B-fragment order per half-group
__device__ uint32_t g_wlf[64 * 4096];           // W lo
__device__ float    g_xp[(size_t)TMAX * IN_F];  // permuted x, fp32

__device__ __forceinline__ uint32_t smem_u32(const void* p) {
    uint32_t a;
    asm("{ .reg .u64 t; cvta.to.shared.u64 t, %1; cvt.u32.u64 %0, t; }" : "=r"(a) : "l"(p));
    return a;
}

__device__ __forceinline__ void split_pack(float v0, float v1, uint32_t& hp, uint32_t& lp) {
    __nv_bfloat16 h0 = __float2bfloat16(v0), h1 = __float2bfloat16(v1);
    __nv_bfloat16 l0 = __float2bfloat16(v0 - __bfloat162float(h0));
    __nv_bfloat16 l1 = __float2bfloat16(v1 - __bfloat162float(h1));
    hp = ((uint32_t)__bfloat16_as_ushort(h1) << 16) | __bfloat16_as_ushort(h0);
    lp = ((uint32_t)__bfloat16_as_ushort(l1) << 16) | __bfloat16_as_ushort(l0);
}

// ---------------- pass 0a: normalize perm (int64-or-int32 -> int32) ----------------
__global__ void convert_perm_kernel(const int* __restrict__ p32) {
    __shared__ int is64;
    if (threadIdx.x == 0) {
        int all0 = 1;
        #pragma unroll
        for (int i = 1; i < 16; i += 2) all0 &= (p32[i] == 0);
        is64 = all0;
    }
    __syncthreads();
    const int w = is64;
    for (int i = threadIdx.x; i < IN_F; i += blockDim.x)
        g_perm[i] = w ? p32[2 * i] : p32[i];
}

// ---------------- pass 0b: W -> split bf16 in mma.sync B-fragment order ----------------
// u32 index e within half-group (64 outputs):
//   r=e&1, lane=(e>>1)&31, ks=(e>>6)&7, nt=e>>9 (0..7)
//   n = nbase + nt*8 + lane/4 ; k0 = ks*16 + 2*(lane&3) + (r?8:0)
__global__ void wprep_kernel(const float* __restrict__ W) {
    const int hg = blockIdx.x;            // 0..63
    const int g = hg >> 1;
    const int nbase = (hg & 1) * 64;
    for (int e = threadIdx.x; e < 4096; e += blockDim.x) {
        const int r    = e & 1;
        const int lane = (e >> 1) & 31;
        const int ks   = (e >> 6) & 7;
        const int nt   = e >> 9;
        const int n    = nbase + nt * 8 + (lane >> 2);
        const int k0   = ks * 16 + 2 * (lane & 3) + (r ? 8 : 0);
        const float v0 = W[((size_t)g * 128 + n) * 128 + k0];
        const float v1 = W[((size_t)g * 128 + n) * 128 + k0 + 1];
        uint32_t hp, lp; split_pack(v0, v1, hp, lp);
        g_whf[hg * 4096 + e] = hp;
        g_wlf[hg * 4096 + e] = lp;
    }
}

// ---------------- pass 1: permute x, fp32 out (coalesced in and out) ----------------
__global__ __launch_bounds__(256) void xprep_kernel(const float* __restrict__ x) {
    __shared__ float row[IN_F];
    const int t = blockIdx.x;
    const float4* src = (const float4*)(x + (size_t)t * IN_F);
    for (int i = threadIdx.x; i < IN_F / 4; i += 256) ((float4*)row)[i] = src[i];
    __syncthreads();
    float4* op = (float4*)(g_xp + (size_t)t * IN_F);
    for (int j = threadIdx.x; j < IN_F / 4; j += 256) {
        float4 o;
        o.x = row[g_perm[4 * j]];
        o.y = row[g_perm[4 * j + 1]];
        o.z = row[g_perm[4 * j + 2]];
        o.w = row[g_perm[4 * j + 3]];
        op[j] = o;
    }
}

// ---------------- pass 2: HMMA block-diagonal GEMM ----------------
// CTA: 128 tokens x 64 outputs (half-group), K=128, split-bf16 3-product.
// smem: A hi/lo (swizzled [128 rows][256B]) 64KB + B hi/lo 32KB = 96KB -> 2 CTA/SM.
#define SM_AH 0
#define SM_AL 32768
#define SM_BH 65536
#define SM_BL 81920
#define SM_SZ 98304

__global__ __launch_bounds__(256, 2)
void bdl_mma_kernel(const float* __restrict__ bias, float* __restrict__ out)
{
    extern __shared__ char smem[];
    const uint32_t sb = smem_u32(smem);
    const int hg = blockIdx.x;
    const int g  = hg >> 1;
    const int t0 = blockIdx.y * TILE_T;
    const int tid = threadIdx.x, lane = tid & 31, wid = tid >> 5;

    // --- A: coalesced float4 LDG of permuted fp32 x; split + swizzled STS.v2 ---
    {
        const float4* xp = (const float4*)g_xp;
        #pragma unroll 4
        for (int e = tid; e < 4096; e += 256) {
            const int t  = e >> 5;          // 0..127
            const int kq = e & 31;          // float4 quad: k = 4*kq..4*kq+3
            const float4 v = xp[(size_t)(t0 + t) * 1024 + g * 32 + kq];
            uint32_t h0, l0, h1, l1;
            split_pack(v.x, v.y, h0, l0);   // pair kp=2kq
            split_pack(v.z, v.w, h1, l1);   // pair kp=2kq+1
            const uint32_t off = (uint32_t)t * 256
                               + ((((uint32_t)kq >> 1) ^ ((uint32_t)t & 7)) << 4)
                               + ((uint32_t)kq & 1) * 8;
            *(uint2*)(smem + SM_AH + off) = make_uint2(h0, h1);
            *(uint2*)(smem + SM_AL + off) = make_uint2(l0, l1);
        }
    }
    // --- B: linear copy of pre-fragmented W (L2-hot) ---
    {
        const uint4* bh = (const uint4*)(g_whf + hg * 4096);
        const uint4* bl = (const uint4*)(g_wlf + hg * 4096);
        uint4* sh = (uint4*)(smem + SM_BH);
        uint4* sl = (uint4*)(smem + SM_BL);
        #pragma unroll 4
        for (int i = tid; i < 1024; i += 256) { sh[i] = bh[i]; sl[i] = bl[i]; }
    }
    __syncthreads();

    // --- mainloop: warp grid 4(m) x 2(n); warp tile 32 tokens x 32 outputs ---
    const int wm = wid & 3;       // rows [wm*32, wm*32+32)
    const int wn = wid >> 2;      // cols [wn*32, wn*32+32)

    float acc[2][4][4];
    #pragma unroll
    for (int mt = 0; mt < 2; ++mt)
        #pragma unroll
        for (int nt = 0; nt < 4; ++nt)
            #pragma unroll
            for (int q = 0; q < 4; ++q) acc[mt][nt][q] = 0.0f;

    #pragma unroll
    for (int ks = 0; ks < 8; ++ks) {
        uint32_t ah[2][4], al[2][4];
        #pragma unroll
        for (int mt = 0; mt < 2; ++mt) {
            const uint32_t row = (uint32_t)(wm * 32 + mt * 16 + (lane & 15));
            const uint32_t c   = (uint32_t)(2 * ks + (lane >> 4));
            const uint32_t aoff = row * 256 + ((c ^ (row & 7)) << 4);
            asm volatile("ldmatrix.sync.aligned.m8n8.x4.shared.b16 {%0,%1,%2,%3}, [%4];"
                         : "=r"(ah[mt][0]), "=r"(ah[mt][1]), "=r"(ah[mt][2]), "=r"(ah[mt][3])
                         : "r"(sb + SM_AH + aoff));
            asm volatile("ldmatrix.sync.aligned.m8n8.x4.shared.b16 {%0,%1,%2,%3}, [%4];"
                         : "=r"(al[mt][0]), "=r"(al[mt][1]), "=r"(al[mt][2]), "=r"(al[mt][3])
                         : "r"(sb + SM_AL + aoff));
        }
        uint32_t bh[4][2], bl[4][2];
        #pragma unroll
        for (int nt = 0; nt < 4; ++nt) {
            const uint32_t boff = (uint32_t)(((wn * 4 + nt) * 8 + ks) * 32 + lane) * 8;
            asm volatile("ld.shared.v2.b32 {%0,%1}, [%2];"
                         : "=r"(bh[nt][0]), "=r"(bh[nt][1]) : "r"(sb + SM_BH + boff));
            asm volatile("ld.shared.v2.b32 {%0,%1}, [%2];"
                         : "=r"(bl[nt][0]), "=r"(bl[nt][1]) : "r"(sb + SM_BL + boff));
        }
        #pragma unroll
        for (int mt = 0; mt < 2; ++mt)
            #pragma unroll
            for (int nt = 0; nt < 4; ++nt) {
                asm volatile(
                    "mma.sync.aligned.m16n8k16.row.col.f32.bf16.bf16.f32 "
                    "{%0,%1,%2,%3}, {%4,%5,%6,%7}, {%8,%9}, {%0,%1,%2,%3};"
                    : "+f"(acc[mt][nt][0]), "+f"(acc[mt][nt][1]),
                      "+f"(acc[mt][nt][2]), "+f"(acc[mt][nt][3])
                    : "r"(ah[mt][0]), "r"(ah[mt][1]), "r"(ah[mt][2]), "r"(ah[mt][3]),
                      "r"(bh[nt][0]), "r"(bh[nt][1]));
                asm volatile(
                    "mma.sync.aligned.m16n8k16.row.col.f32.bf16.bf16.f32 "
                    "{%0,%1,%2,%3}, {%4,%5,%6,%7}, {%8,%9}, {%0,%1,%2,%3};"
                    : "+f"(acc[mt][nt][0]), "+f"(acc[mt][nt][1]),
                      "+f"(acc[mt][nt][2]), "+f"(acc[mt][nt][3])
                    : "r"(ah[mt][0]), "r"(ah[mt][1]), "r"(ah[mt][2]), "r"(ah[mt][3]),
                      "r"(bl[nt][0]), "r"(bl[nt][1]));
                asm volatile(
                    "mma.sync.aligned.m16n8k16.row.col.f32.bf16.bf16.f32 "
                    "{%0,%1,%2,%3}, {%4,%5,%6,%7}, {%8,%9}, {%0,%1,%2,%3};"
                    : "+f"(acc[mt][nt][0]), "+f"(acc[mt][nt][1]),
                      "+f"(acc[mt][nt][2]), "+f"(acc[mt][nt][3])
                    : "r"(al[mt][0]), "r"(al[mt][1]), "r"(al[mt][2]), "r"(al[mt][3]),
                      "r"(bh[nt][0]), "r"(bh[nt][1]));
            }
    }

    // --- epilogue: bias + st.v2 (c-fragment layout) ---
    const int colbase = g * 128 + (hg & 1) * 64 + wn * 32;
    #pragma unroll
    for (int nt = 0; nt < 4; ++nt) {
        const int col = colbase + nt * 8 + 2 * (lane & 3);
        const float b0 = bias[col], b1 = bias[col + 1];
        #pragma unroll
        for (int mt = 0; mt < 2; ++mt) {
            const int r0 = t0 + wm * 32 + mt * 16 + (lane >> 2);
            float2 v0 = make_float2(acc[mt][nt][0] + b0, acc[mt][nt][1] + b1);
            float2 v1 = make_float2(acc[mt][nt][2] + b0, acc[mt][nt][3] + b1);
            *(float2*)(out + (size_t)r0 * IN_F + col)       = v0;
            *(float2*)(out + (size_t)(r0 + 8) * IN_F + col) = v1;
        }
    }
}

// ---------------- launch ----------------
extern "C" void kernel_launch(void* const* d_in, const int* in_sizes, int n_in,
                              void* d_out, int out_size)
{
    const float* x    = (const float*)d_in[0];
    const int*   perm = (const int*)d_in[1];
    const float* W    = (const float*)d_in[2];
    const float* bias = (const float*)d_in[3];
    float* out = (float*)d_out;

    const int T = in_sizes[0] / IN_F;   // 16384

    convert_perm_kernel<<<1, 1024>>>(perm);
    wprep_kernel<<<64, 256>>>(W);
    xprep_kernel<<<T, 256>>>(x);

    cudaFuncSetAttribute(bdl_mma_kernel,
                         cudaFuncAttributeMaxDynamicSharedMemorySize, SM_SZ);
    dim3 grid(64, T / TILE_T);
    bdl_mma_kernel<<<grid, 256, SM_SZ>>>(bias, out);
}